// round 7
// baseline (speedup 1.0000x reference)
#include <cuda_runtime.h>
#include <stdint.h>

#define N_WORDS   8
#define HASH_BITS 11
#define HASH_SIZE (1 << HASH_BITS)   // 2048 slots (load factor ~0.49)
#define HASH_MASK (HASH_SIZE - 1)
#define THREADS   256

// Global scratch: open-addressing hash table, slot = class idx or -1.
__device__ int g_table[HASH_SIZE];

__device__ __forceinline__ uint32_t hash_words(const uint32_t k[N_WORDS]) {
    uint32_t h = 2166136261u;
    #pragma unroll
    for (int j = 0; j < N_WORDS; ++j) h = (h ^ k[j]) * 16777619u;
    h ^= h >> 15; h *= 0x2c1b3c6du;
    h ^= h >> 12; h *= 0x297a2d39u;
    h ^= h >> 15;
    return h;
}

template <bool VEC>
__device__ __forceinline__ void load_key(const int* __restrict__ p, uint32_t k[N_WORDS]) {
    if (VEC) {
        int4 a = __ldg(reinterpret_cast<const int4*>(p));
        int4 b = __ldg(reinterpret_cast<const int4*>(p) + 1);
        k[0] = (uint32_t)a.x; k[1] = (uint32_t)a.y; k[2] = (uint32_t)a.z; k[3] = (uint32_t)a.w;
        k[4] = (uint32_t)b.x; k[5] = (uint32_t)b.y; k[6] = (uint32_t)b.z; k[7] = (uint32_t)b.w;
    } else {
        #pragma unroll
        for (int j = 0; j < N_WORDS; ++j) k[j] = (uint32_t)__ldg(p + j);
    }
}

// ---- Kernel 1: build the table once (single block). ----
template <bool VEC>
__global__ void build_kernel(const int* __restrict__ classes, int n_classes) {
    const int tid = threadIdx.x;
    for (int i = tid; i < HASH_SIZE; i += blockDim.x) g_table[i] = -1;
    __syncthreads();
    for (int c = tid; c < n_classes; c += blockDim.x) {
        uint32_t k[N_WORDS];
        load_key<VEC>(classes + (size_t)c * N_WORDS, k);
        uint32_t h = hash_words(k) & HASH_MASK;
        for (int p = 0; p < HASH_SIZE; ++p) {
            if (atomicCAS(&g_table[h], -1, c) == -1) break;  // keys unique
            h = (h + 1) & HASH_MASK;
        }
    }
}

// ---- Kernel 2: pure lookup, no smem, no syncs. ----
template <bool VEC>
__global__ __launch_bounds__(THREADS)
void lookup_kernel(const int* __restrict__ x,
                   const int* __restrict__ classes,
                   float* __restrict__ out, int n_rows, int n_classes) {
    const int r = blockIdx.x * THREADS + threadIdx.x;
    if (r >= n_rows) return;

    uint32_t k[N_WORDS];
    load_key<VEC>(x + (size_t)r * N_WORDS, k);
    uint32_t h = hash_words(k) & HASH_MASK;

    int result = -1;
    for (int p = 0; p < HASH_SIZE; ++p) {
        int c = __ldg(&g_table[h]);
        if (c < 0) break;
        uint32_t ck[N_WORDS];
        load_key<VEC>(classes + (size_t)c * N_WORDS, ck);
        bool match = true;
        #pragma unroll
        for (int j = 0; j < N_WORDS; ++j) match &= (ck[j] == k[j]);
        if (match) { result = c; break; }
        h = (h + 1) & HASH_MASK;
    }

    // Fallback (key guaranteed present; keeps argmax semantics if not).
    if (result < 0) {
        for (int c = 0; c < n_classes; ++c) {
            uint32_t ck[N_WORDS];
            load_key<VEC>(classes + (size_t)c * N_WORDS, ck);
            bool match = true;
            #pragma unroll
            for (int j = 0; j < N_WORDS; ++j) match &= (ck[j] == k[j]);
            if (match) { result = c; break; }
        }
        if (result < 0) result = 0;
    }

    out[r] = (float)result;
}

extern "C" void kernel_launch(void* const* d_in, const int* in_sizes, int n_in,
                              void* d_out, int out_size) {
    // x is the large input (one output per row); classes_table is the small one.
    int xi = 0, ci = 1;
    if (n_in >= 2 && in_sizes[1] > in_sizes[0]) { xi = 1; ci = 0; }

    const int* x       = (const int*)d_in[xi];
    const int* classes = (const int*)d_in[ci];
    float* out         = (float*)d_out;

    int rows_from_x = in_sizes[xi] / N_WORDS;
    int n_rows = (out_size < rows_from_x) ? out_size : rows_from_x;
    int n_classes = in_sizes[ci] / N_WORDS;

    int blocks = (n_rows + THREADS - 1) / THREADS;
    if (blocks < 1) blocks = 1;

    const bool vec = ((((uintptr_t)x) & 15u) == 0) && ((((uintptr_t)classes) & 15u) == 0);
    if (vec) {
        build_kernel<true><<<1, 1024>>>(classes, n_classes);
        lookup_kernel<true><<<blocks, THREADS>>>(x, classes, out, n_rows, n_classes);
    } else {
        build_kernel<false><<<1, 1024>>>(classes, n_classes);
        lookup_kernel<false><<<blocks, THREADS>>>(x, classes, out, n_rows, n_classes);
    }
}

// round 8
// speedup vs baseline: 2.1195x; 2.1195x over previous
#include <cuda_runtime.h>
#include <stdint.h>

#define N_WORDS     8
#define HASH_BITS   11
#define HASH_SIZE   (1 << HASH_BITS)   // 2048 slots x 16B = 32 KB smem
#define HASH_MASK   (HASH_SIZE - 1)
#define THREADS     256
#define ROWS_PER_T  2
#define BLOCK_ROWS  (THREADS * ROWS_PER_T)
#define EMPTY_IDX   0xFFFFFFFFu

__device__ __forceinline__ uint32_t hash_slot(const uint32_t k[N_WORDS]) {
    uint32_t h = 2166136261u;
    #pragma unroll
    for (int j = 0; j < N_WORDS; ++j) h = (h ^ k[j]) * 16777619u;
    h ^= h >> 15; h *= 0x2c1b3c6du;
    h ^= h >> 12; h *= 0x297a2d39u;
    h ^= h >> 15;
    return h & HASH_MASK;
}

__device__ __forceinline__ uint64_t hash_fp64(const uint32_t k[N_WORDS]) {
    // Independent 64-bit fingerprint (splitmix-style).
    uint64_t f = 0x9E3779B97F4A7C15ull;
    #pragma unroll
    for (int j = 0; j < N_WORDS; ++j) {
        f = (f ^ (uint64_t)k[j]) * 0xBF58476D1CE4E5B9ull;
        f ^= f >> 27;
    }
    f *= 0x94D049BB133111EBull;
    f ^= f >> 31;
    return f;
}

template <bool VEC>
__device__ __forceinline__ void load_key(const int* __restrict__ p, uint32_t k[N_WORDS]) {
    if (VEC) {
        int4 a = __ldg(reinterpret_cast<const int4*>(p));
        int4 b = __ldg(reinterpret_cast<const int4*>(p) + 1);
        k[0] = (uint32_t)a.x; k[1] = (uint32_t)a.y; k[2] = (uint32_t)a.z; k[3] = (uint32_t)a.w;
        k[4] = (uint32_t)b.x; k[5] = (uint32_t)b.y; k[6] = (uint32_t)b.z; k[7] = (uint32_t)b.w;
    } else {
        #pragma unroll
        for (int j = 0; j < N_WORDS; ++j) k[j] = (uint32_t)__ldg(p + j);
    }
}

template <bool VEC>
__global__ __launch_bounds__(THREADS)
void encode_kernel(const int* __restrict__ x,
                   const int* __restrict__ classes,
                   float* __restrict__ out,
                   int n_rows, int n_classes) {
    // slot = {fp_lo, fp_hi, class_idx (EMPTY_IDX if free), pad}
    __shared__ uint4 s_tab[HASH_SIZE];

    const int tid = threadIdx.x;

    // 1) Init (8 slots per thread).
    #pragma unroll
    for (int i = tid; i < HASH_SIZE; i += THREADS)
        s_tab[i] = make_uint4(0u, 0u, EMPTY_IDX, 0u);
    __syncthreads();

    // 2) Build: hash class rows straight from L2 (coalesced; ~4 rows/thread).
    const int nc_ins = (n_classes < HASH_SIZE) ? n_classes : HASH_SIZE - 1;
    for (int c = tid; c < nc_ins; c += THREADS) {
        uint32_t k[N_WORDS];
        load_key<VEC>(classes + (size_t)c * N_WORDS, k);
        uint32_t h = hash_slot(k);
        uint64_t f = hash_fp64(k);
        for (int p = 0; p < HASH_SIZE; ++p) {
            uint32_t* idx_word = &(reinterpret_cast<uint32_t*>(&s_tab[h]))[2];
            if (atomicCAS(idx_word, EMPTY_IDX, (uint32_t)c) == EMPTY_IDX) {
                s_tab[h].x = (uint32_t)(f & 0xFFFFFFFFull);
                s_tab[h].y = (uint32_t)(f >> 32);
                break;
            }
            h = (h + 1) & HASH_MASK;
        }
    }
    __syncthreads();

    // 3) Lookup: 2 independent rows per thread (MLP).
    const int base = blockIdx.x * BLOCK_ROWS + tid;

    uint32_t k0[N_WORDS], k1[N_WORDS];
    const int r0 = base;
    const int r1 = base + THREADS;
    const bool v0 = (r0 < n_rows);
    const bool v1 = (r1 < n_rows);

    if (v0) load_key<VEC>(x + (size_t)r0 * N_WORDS, k0);
    if (v1) load_key<VEC>(x + (size_t)r1 * N_WORDS, k1);

    #pragma unroll
    for (int q = 0; q < 2; ++q) {
        const bool valid = q ? v1 : v0;
        if (!valid) continue;
        const uint32_t* k = q ? k1 : k0;
        const int r = q ? r1 : r0;

        uint32_t h = hash_slot(k);
        uint64_t f = hash_fp64(k);
        uint32_t f_lo = (uint32_t)(f & 0xFFFFFFFFull);
        uint32_t f_hi = (uint32_t)(f >> 32);

        int result = -1;
        for (int p = 0; p < HASH_SIZE; ++p) {
            uint4 e = s_tab[h];                 // LDS.128
            if (e.z == EMPTY_IDX) break;
            if (e.x == f_lo && e.y == f_hi) { result = (int)e.z; break; }
            h = (h + 1) & HASH_MASK;
        }

        // Exact fallback: linear scan of global classes (covers fp-miss and
        // n_classes > table capacity; first ascending match == argmax).
        if (result < 0) {
            for (int c = 0; c < n_classes; ++c) {
                uint32_t ck[N_WORDS];
                load_key<VEC>(classes + (size_t)c * N_WORDS, ck);
                bool match = true;
                #pragma unroll
                for (int j = 0; j < N_WORDS; ++j) match &= (ck[j] == k[j]);
                if (match) { result = c; break; }
            }
            if (result < 0) result = 0;
        }

        out[r] = (float)result;
    }
}

extern "C" void kernel_launch(void* const* d_in, const int* in_sizes, int n_in,
                              void* d_out, int out_size) {
    // x is the large input (one output per row); classes_table is the small one.
    int xi = 0, ci = 1;
    if (n_in >= 2 && in_sizes[1] > in_sizes[0]) { xi = 1; ci = 0; }

    const int* x       = (const int*)d_in[xi];
    const int* classes = (const int*)d_in[ci];
    float* out         = (float*)d_out;

    int rows_from_x = in_sizes[xi] / N_WORDS;
    int n_rows = (out_size < rows_from_x) ? out_size : rows_from_x;
    int n_classes = in_sizes[ci] / N_WORDS;

    int blocks = (n_rows + BLOCK_ROWS - 1) / BLOCK_ROWS;
    if (blocks < 1) blocks = 1;

    const bool vec = ((((uintptr_t)x) & 15u) == 0) && ((((uintptr_t)classes) & 15u) == 0);
    if (vec) encode_kernel<true ><<<blocks, THREADS>>>(x, classes, out, n_rows, n_classes);
    else     encode_kernel<false><<<blocks, THREADS>>>(x, classes, out, n_rows, n_classes);
}

// round 9
// speedup vs baseline: 2.5964x; 1.2250x over previous
#include <cuda_runtime.h>
#include <stdint.h>

#define N_WORDS    8
#define HASH_BITS  11
#define HASH_SIZE  (1 << HASH_BITS)    // 2048 slots x 8B = 16 KB smem
#define HASH_MASK  (HASH_SIZE - 1)
#define THREADS    1024
#define NUM_BLOCKS 148                 // one wave on GB300

// Slot layout: [63] occupied | [62:11] fingerprint (52b) | [10:0] class idx
#define IDX_BITS   11
#define IDX_MASK   ((1ull << IDX_BITS) - 1ull)
#define OCC_BIT    (1ull << 63)
#define FP_MASK    (~(OCC_BIT | IDX_MASK))   // bits [62:11]

__device__ __forceinline__ uint32_t hash_slot(const uint32_t k[N_WORDS]) {
    uint32_t h = 2166136261u;
    #pragma unroll
    for (int j = 0; j < N_WORDS; ++j) h = (h ^ k[j]) * 16777619u;
    h ^= h >> 15; h *= 0x2c1b3c6du;
    h ^= h >> 12; h *= 0x297a2d39u;
    h ^= h >> 15;
    return h & HASH_MASK;
}

__device__ __forceinline__ uint64_t hash_fp(const uint32_t k[N_WORDS]) {
    uint64_t f = 0x9E3779B97F4A7C15ull;
    #pragma unroll
    for (int j = 0; j < N_WORDS; ++j) {
        f = (f ^ (uint64_t)k[j]) * 0xBF58476D1CE4E5B9ull;
        f ^= f >> 27;
    }
    f *= 0x94D049BB133111EBull;
    f ^= f >> 31;
    return f;
}

template <bool VEC>
__device__ __forceinline__ void load_key(const int* __restrict__ p, uint32_t k[N_WORDS]) {
    if (VEC) {
        int4 a = __ldg(reinterpret_cast<const int4*>(p));
        int4 b = __ldg(reinterpret_cast<const int4*>(p) + 1);
        k[0] = (uint32_t)a.x; k[1] = (uint32_t)a.y; k[2] = (uint32_t)a.z; k[3] = (uint32_t)a.w;
        k[4] = (uint32_t)b.x; k[5] = (uint32_t)b.y; k[6] = (uint32_t)b.z; k[7] = (uint32_t)b.w;
    } else {
        #pragma unroll
        for (int j = 0; j < N_WORDS; ++j) k[j] = (uint32_t)__ldg(p + j);
    }
}

template <bool VEC>
__global__ __launch_bounds__(THREADS)
void encode_kernel(const int* __restrict__ x,
                   const int* __restrict__ classes,
                   float* __restrict__ out,
                   int n_rows, int n_classes) {
    __shared__ unsigned long long s_tab[HASH_SIZE];

    const int tid = threadIdx.x;

    // 1) Init: 2 slots per thread.
    #pragma unroll
    for (int i = tid; i < HASH_SIZE; i += THREADS) s_tab[i] = 0ull;
    __syncthreads();

    // 2) Build: ~1 class row per thread, straight from L2.
    const int nc_ins = (n_classes < HASH_SIZE) ? n_classes : HASH_SIZE - 1;
    for (int c = tid; c < nc_ins; c += THREADS) {
        uint32_t k[N_WORDS];
        load_key<VEC>(classes + (size_t)c * N_WORDS, k);
        uint32_t h = hash_slot(k);
        unsigned long long entry =
            OCC_BIT | (hash_fp(k) & FP_MASK) | ((unsigned long long)c & IDX_MASK);
        for (int p = 0; p < HASH_SIZE; ++p) {
            if (atomicCAS(&s_tab[h], 0ull, entry) == 0ull) break;  // keys unique
            h = (h + 1) & HASH_MASK;
        }
    }
    __syncthreads();

    // 3) Lookup: grid-stride (<=1 row per thread at N=100k, general otherwise).
    const int stride = gridDim.x * THREADS;
    for (int r = blockIdx.x * THREADS + tid; r < n_rows; r += stride) {
        uint32_t k[N_WORDS];
        load_key<VEC>(x + (size_t)r * N_WORDS, k);

        uint32_t h = hash_slot(k);
        unsigned long long pattern = OCC_BIT | (hash_fp(k) & FP_MASK);

        int result = -1;
        for (int p = 0; p < HASH_SIZE; ++p) {
            unsigned long long e = s_tab[h];          // LDS.64
            if (e == 0ull) break;
            if ((e & ~IDX_MASK) == pattern) { result = (int)(e & IDX_MASK); break; }
            h = (h + 1) & HASH_MASK;
        }

        // Exact fallback (fp-miss or n_classes beyond table capacity):
        // first ascending match == argmax semantics; 0 if none.
        if (result < 0) {
            for (int c = 0; c < n_classes; ++c) {
                uint32_t ck[N_WORDS];
                load_key<VEC>(classes + (size_t)c * N_WORDS, ck);
                bool match = true;
                #pragma unroll
                for (int j = 0; j < N_WORDS; ++j) match &= (ck[j] == k[j]);
                if (match) { result = c; break; }
            }
            if (result < 0) result = 0;
        }

        out[r] = (float)result;
    }
}

extern "C" void kernel_launch(void* const* d_in, const int* in_sizes, int n_in,
                              void* d_out, int out_size) {
    // x is the large input (one output per row); classes_table is the small one.
    int xi = 0, ci = 1;
    if (n_in >= 2 && in_sizes[1] > in_sizes[0]) { xi = 1; ci = 0; }

    const int* x       = (const int*)d_in[xi];
    const int* classes = (const int*)d_in[ci];
    float* out         = (float*)d_out;

    int rows_from_x = in_sizes[xi] / N_WORDS;
    int n_rows = (out_size < rows_from_x) ? out_size : rows_from_x;
    int n_classes = in_sizes[ci] / N_WORDS;

    int blocks_needed = (n_rows + THREADS - 1) / THREADS;
    int blocks = (blocks_needed < NUM_BLOCKS) ? blocks_needed : NUM_BLOCKS;
    if (blocks < 1) blocks = 1;

    const bool vec = ((((uintptr_t)x) & 15u) == 0) && ((((uintptr_t)classes) & 15u) == 0);
    if (vec) encode_kernel<true ><<<blocks, THREADS>>>(x, classes, out, n_rows, n_classes);
    else     encode_kernel<false><<<blocks, THREADS>>>(x, classes, out, n_rows, n_classes);
}